// round 9
// baseline (speedup 1.0000x reference)
#include <cuda_runtime.h>

#define IMG_W 512
#define IMG_H 512
#define N_IMG 48            // 16 batch * 3 channels
#define HT 8                // output rows per block strip
#define N_STRIPS (IMG_H / HT)
#define NBLK (N_STRIPS * N_IMG)
#define SW 528              // smem columns: s = x+8; float4-aligned rows
#define NT 256              // 8 warps
#define SM_FLOATS (4 * HT * SW)
#define SMEM_BYTES ((SM_FLOATS + 8) * 4)

// zero-initialized at module load; last block of each launch resets them,
// so every graph replay starts from zero (deterministic).
__device__ double g_acc;
__device__ unsigned int g_cnt;

#define WG_INIT {0.00102838f, 0.00759876f, 0.03600077f, 0.10936069f, \
                 0.21300554f, 0.26601173f, 0.21300554f, 0.10936069f, \
                 0.03600077f, 0.00759876f, 0.00102838f}

__global__ void __launch_bounds__(NT, 3) ssim_fused(const float* __restrict__ pred,
                                                    const float* __restrict__ tgt,
                                                    float* __restrict__ out) {
    extern __shared__ float sm[];
    float* wsum = sm + SM_FLOATS;
    const float wg[11] = WG_INIT;

    const int img  = blockIdx.y;
    const int row0 = blockIdx.x * HT;
    const float* P = pred + (size_t)img * (IMG_W * IMG_H);
    const float* T = tgt  + (size_t)img * (IMG_W * IMG_H);
    const bool interior = (row0 >= 5) && (row0 + HT + 5 <= IMG_H);

    // -------- Vertical pass (streaming accumulators): global -> smem --------
    for (int s = threadIdx.x; s < SW; s += NT) {
        const int x = s - 8;
        if (x < 0 || x >= IMG_W) {
            #pragma unroll
            for (int r = 0; r < HT; r++) {
                sm[(0 * HT + r) * SW + s] = 0.f;
                sm[(1 * HT + r) * SW + s] = 0.f;
                sm[(2 * HT + r) * SW + s] = 0.f;
                sm[(3 * HT + r) * SW + s] = 0.f;
            }
            continue;
        }
        float mp[HT], mt[HT], ms[HT], mq[HT];
        #pragma unroll
        for (int r = 0; r < HT; r++) { mp[r] = 0.f; mt[r] = 0.f; ms[r] = 0.f; mq[r] = 0.f; }

        const float* pc = P + (row0 - 5) * IMG_W + x;
        const float* tc = T + (row0 - 5) * IMG_W + x;
        #pragma unroll
        for (int i = 0; i < HT + 10; i++) {
            float p, t;
            if (interior) {
                p = pc[i * IMG_W];
                t = tc[i * IMG_W];
            } else {
                const int row = row0 - 5 + i;
                const bool ok = (row >= 0) && (row < IMG_H);
                p = ok ? P[row * IMG_W + x] : 0.f;
                t = ok ? T[row * IMG_W + x] : 0.f;
            }
            const float s2 = fmaf(t, t, p * p);   // p^2 + t^2 combined channel
            const float q  = p * t;               // computed once per input row
            // input row i feeds outputs r where 0 <= i-r <= 10 (weight wg[i-r])
            #pragma unroll
            for (int r = 0; r < HT; r++) {
                const int k = i - r;
                if (k >= 0 && k <= 10) {           // folds at compile time
                    mp[r] = fmaf(wg[k], p,  mp[r]);
                    mt[r] = fmaf(wg[k], t,  mt[r]);
                    ms[r] = fmaf(wg[k], s2, ms[r]);
                    mq[r] = fmaf(wg[k], q,  mq[r]);
                }
            }
        }
        #pragma unroll
        for (int r = 0; r < HT; r++) {
            sm[(0 * HT + r) * SW + s] = mp[r];
            sm[(1 * HT + r) * SW + s] = mt[r];
            sm[(2 * HT + r) * SW + s] = ms[r];
            sm[(3 * HT + r) * SW + s] = mq[r];
        }
    }
    __syncthreads();

    // -------- Horizontal pass (4-wide quads) + SSIM formula + reduce --------
    const float C1 = 1e-4f, C2 = 9e-4f;
    float acc = 0.f;
    for (int task = threadIdx.x; task < HT * (IMG_W / 4); task += NT) {
        const int r = task >> 7;       // row within strip
        const int q = task & 127;      // quad: outputs x0 = 4q .. 4q+3
        float h[4][4];
        #pragma unroll
        for (int ch = 0; ch < 4; ch++) {
            const float4* rowp = (const float4*)(sm + (ch * HT + r) * SW);
            float v[20];
            #pragma unroll
            for (int b = 0; b < 5; b++) {
                float4 f = rowp[q + b];   // s = 4q..4q+19 covers taps [4q+3, 4q+16]
                v[4 * b + 0] = f.x; v[4 * b + 1] = f.y;
                v[4 * b + 2] = f.z; v[4 * b + 3] = f.w;
            }
            #pragma unroll
            for (int j = 0; j < 4; j++) {
                float a = 0.f;
                #pragma unroll
                for (int k = 0; k < 11; k++) a = fmaf(wg[k], v[3 + j + k], a);
                h[ch][j] = a;
            }
        }
        #pragma unroll
        for (int j = 0; j < 4; j++) {
            float mx  = h[0][j], my = h[1][j];
            float mx2 = mx * mx, my2 = my * my, mxy = mx * my;
            float sgs  = h[2][j] - mx2 - my2;   // sg_x + sg_y
            float sgxy = h[3][j] - mxy;
            float num = (2.f * mxy + C1) * (2.f * sgxy + C2);
            float den = (mx2 + my2 + C1) * (sgs + C2);
            acc += __fdividef(num, den);
        }
    }

    // block reduction
    #pragma unroll
    for (int off = 16; off; off >>= 1)
        acc += __shfl_down_sync(0xffffffffu, acc, off);
    if ((threadIdx.x & 31) == 0) wsum[threadIdx.x >> 5] = acc;
    __syncthreads();

    if (threadIdx.x == 0) {
        float s = 0.f;
        #pragma unroll
        for (int i = 0; i < NT / 32; i++) s += wsum[i];
        atomicAdd(&g_acc, (double)s);
        __threadfence();
        unsigned int t = atomicAdd(&g_cnt, 1u);
        if (t == NBLK - 1) {
            double tot = atomicAdd(&g_acc, 0.0);   // coherent read (returns old)
            out[0] = 1.0f - (float)(tot / ((double)N_IMG * IMG_W * IMG_H));
            g_acc = 0.0;    // reset for next graph replay
            g_cnt = 0u;
        }
    }
}

extern "C" void kernel_launch(void* const* d_in, const int* in_sizes, int n_in,
                              void* d_out, int out_size) {
    const float* pred = (const float*)d_in[0];
    const float* tgt  = (const float*)d_in[1];

    // 66 KB dynamic smem > 48 KB default: opt-in (host attribute, capture-safe)
    cudaFuncSetAttribute(ssim_fused, cudaFuncAttributeMaxDynamicSharedMemorySize,
                         SMEM_BYTES);

    dim3 grid(N_STRIPS, N_IMG);
    ssim_fused<<<grid, NT, SMEM_BYTES>>>(pred, tgt, (float*)d_out);
}